// round 15
// baseline (speedup 1.0000x reference)
#include <cuda_runtime.h>

// CRF forward (log partition) on GB300 — round 14 (R13 design, buffer fixed).
// One 32-thread CTA per batch; lane l = tag l (all-read layout, NO shuffles
// in the recurrence loop).
//
// Linear-domain recurrence:
//   acc_i = sum_j E[i][j] * p_j     (16x fma.rn.f32x2 per lane, E in regs)
//   p_i   = acc_i * d_i,  d_i = exp(emit_t_i)  (one MUFU per step)
// Exact pow2 rescale every 4 steps from exponent(p[0]) — every lane reads
// p[0] identically from smem (first word of the LDS), so the shift is
// uniform with zero cross-lane communication, built off the critical path.
//
// Buffering: step t stores p to sp[t&1] and loads the full vector from the
// SAME buffer (BAR orders store->load). Step t+1 targets the other buffer,
// so its stores can never clobber words still being read by step t.

#define T_TAGS 32
#define START_TAG 30
#define STOP_TAG 31
#define LOG2E 1.4426950408889634f
#define LN2   0.6931471805599453f
#define PF 8   // emission prefetch depth

__device__ __forceinline__ float ex2a(float x) {
    float r; asm("ex2.approx.f32 %0, %1;" : "=f"(r) : "f"(x)); return r;
}
__device__ __forceinline__ float lg2a(float x) {
    float r; asm("lg2.approx.f32 %0, %1;" : "=f"(r) : "f"(x)); return r;
}
__device__ __forceinline__ unsigned long long pk2(float lo, float hi) {
    unsigned long long r;
    asm("mov.b64 %0, {%1, %2};" : "=l"(r) : "f"(lo), "f"(hi));
    return r;
}
__device__ __forceinline__ void upk2(unsigned long long v, float& lo, float& hi) {
    asm("mov.b64 {%0, %1}, %2;" : "=f"(lo), "=f"(hi) : "l"(v));
}
__device__ __forceinline__ unsigned long long fma2(unsigned long long a,
                                                   unsigned long long b,
                                                   unsigned long long c) {
    unsigned long long d;
    asm("fma.rn.f32x2 %0, %1, %2, %3;" : "=l"(d) : "l"(a), "l"(b), "l"(c));
    return d;
}
__device__ __forceinline__ unsigned long long add2(unsigned long long a,
                                                   unsigned long long b) {
    unsigned long long d;
    asm("add.rn.f32x2 %0, %1, %2;" : "=l"(d) : "l"(a), "l"(b));
    return d;
}

// One recurrence step. RESCALE selects the (t&3)==3 variant.
// buf is BOTH the store target and the load source for this step.
template <bool RESCALE>
__device__ __forceinline__ void crf_step(
    float em, float& p, int& ishift,
    const unsigned long long (&E2)[16],
    float* buf, int lane)
{
    // d = exp(emit) — issued before the exchange so MUFU latency hides
    float d = ex2a(em * LOG2E);

    buf[lane] = p;
    __syncthreads();   // 1-warp CTA: ~3-cycle BAR, drains the STS

    const ulonglong2* q = reinterpret_cast<const ulonglong2*>(buf);
    ulonglong2 v0 = q[0], v1 = q[1], v2 = q[2], v3 = q[3];

    float rs = 1.0f;
    if (RESCALE) {
        // exponent of p[0] (identical on all lanes) — exact pow2 shift
        float p0lo, p0hi;
        upk2(v0.x, p0lo, p0hi);
        int k = ((__float_as_int(p0lo) >> 23) & 0xff) - 127;
        ishift += k;
        rs = __int_as_float((127 - k) << 23);   // 2^-k, exact
    }

    // 16 fma2 in 4 independent chains of depth 4
    unsigned long long A, B, C, D;
    A = fma2(E2[0],  v0.x, 0ull);
    B = fma2(E2[1],  v0.y, 0ull);
    C = fma2(E2[2],  v1.x, 0ull);
    D = fma2(E2[3],  v1.y, 0ull);
    A = fma2(E2[4],  v2.x, A);
    B = fma2(E2[5],  v2.y, B);
    C = fma2(E2[6],  v3.x, C);
    D = fma2(E2[7],  v3.y, D);
    ulonglong2 w0 = q[4], w1 = q[5], w2 = q[6], w3 = q[7];
    A = fma2(E2[8],  w0.x, A);
    B = fma2(E2[9],  w0.y, B);
    C = fma2(E2[10], w1.x, C);
    D = fma2(E2[11], w1.y, D);
    A = fma2(E2[12], w2.x, A);
    B = fma2(E2[13], w2.y, B);
    C = fma2(E2[14], w3.x, C);
    D = fma2(E2[15], w3.y, D);

    unsigned long long AB = add2(A, B);
    unsigned long long CD = add2(C, D);
    unsigned long long T  = add2(AB, CD);
    float lo, hi;
    upk2(T, lo, hi);
    float acc = lo + hi;

    p = RESCALE ? acc * (d * rs) : acc * d;
}

template <int SC>
__global__ __launch_bounds__(32, 16)
void crf_fwd_kernel(const float* __restrict__ feats,
                    const float* __restrict__ trans,
                    float* __restrict__ out,
                    int S_rt) {
    const int S = (SC > 0) ? SC : S_rt;
    const int lane = threadIdx.x;
    const int b = blockIdx.x;

    __shared__ __align__(16) float sp[2][T_TAGS];

    // ---- E in registers: lane = row, 16 packed column-pairs ----
    unsigned long long E2[16];
    {
        const float* tr = trans + lane * T_TAGS;
        #pragma unroll
        for (int m = 0; m < 16; m++)
            E2[m] = pk2(ex2a(tr[2 * m] * LOG2E), ex2a(tr[2 * m + 1] * LOG2E));
    }
    // STOP-row factor for termination (exp(-1e4) -> 0, correct)
    const float estop = ex2a(trans[STOP_TAG * T_TAGS + lane] * LOG2E);

    // ---- Emission register pipeline ----
    const float* f = feats + (size_t)b * (size_t)S * T_TAGS + lane;
    float ebuf[PF];
    #pragma unroll
    for (int k = 0; k < PF; k++) ebuf[k] = f[(size_t)k * T_TAGS];

    // ---- State: p = exp(alpha - ln2*ishift), one-hot at START ----
    float p = (lane == START_TAG) ? 1.0f : 0.0f;
    int ishift = 0;

    if (SC == 512) {
        // main loop: 504 iters (63 x 8), unconditional prefetch; 8-iter tail
        #pragma unroll 8
        for (int t = 0; t < 512 - PF; t++) {
            float em = ebuf[t & (PF - 1)];
            ebuf[t & (PF - 1)] = f[(size_t)(t + PF) * T_TAGS];
            if ((t & 3) == 3)
                crf_step<true >(em, p, ishift, E2, sp[t & 1], lane);
            else
                crf_step<false>(em, p, ishift, E2, sp[t & 1], lane);
        }
        #pragma unroll
        for (int t = 512 - PF; t < 512; t++) {
            float em = ebuf[t & (PF - 1)];
            if ((t & 3) == 3)
                crf_step<true >(em, p, ishift, E2, sp[t & 1], lane);
            else
                crf_step<false>(em, p, ishift, E2, sp[t & 1], lane);
        }
    } else {
        #pragma unroll 4
        for (int t = 0; t < S; t++) {
            float em = ebuf[t & (PF - 1)];
            if (t + PF < S) ebuf[t & (PF - 1)] = f[(size_t)(t + PF) * T_TAGS];
            if ((t & 3) == 3)
                crf_step<true >(em, p, ishift, E2, sp[t & 1], lane);
            else
                crf_step<false>(em, p, ishift, E2, sp[t & 1], lane);
        }
    }

    // ---- Termination: logZ = ln2 * (ishift + log2(sum_j p_j * estop_j)) ----
    float v = p * estop;
    #pragma unroll
    for (int off = 16; off; off >>= 1)
        v += __shfl_xor_sync(0xffffffffu, v, off);
    if (lane == 0) out[b] = ((float)ishift + lg2a(v)) * LN2;
}

extern "C" void kernel_launch(void* const* d_in, const int* in_sizes, int n_in,
                              void* d_out, int out_size) {
    const float* feats = (const float*)d_in[0];   // [B, S, 32]
    const float* trans = (const float*)d_in[1];   // [32, 32]
    float* out = (float*)d_out;                   // [B]

    const int B = out_size;
    const int S = in_sizes[0] / (B * T_TAGS);

    if (S == 512) {
        crf_fwd_kernel<512><<<B, 32>>>(feats, trans, out, S);
    } else {
        crf_fwd_kernel<0><<<B, 32>>>(feats, trans, out, S);
    }
}